// round 14
// baseline (speedup 1.0000x reference)
#include <cuda_runtime.h>
#include <cuda_bf16.h>
#include <math.h>

// Problem constants
#define NROWS 65536
#define PDIM  512
#define HDIM  256
#define DIN   768
#define D1    200
#define D2    100
#define D3    100
#define DOUT  512

#define ROWS  64      // rows per block
#define TH    512     // threads per block (16 warps: 4 row-groups x 4 n-quarters)

// ---- SMEM layout in uint2 units (one uint2 = {hi bf16x2, lo bf16x2} for one k-pair).
// All pitches === 4 (mod 16) -> conflict-free LDS.64 fragment loads.
#define U2_H2   0              // h2: 64 x 68
#define U2_H3   4352           // h3: 64 x 68
#define U2_W    8704           // weight staging: W12 104x116 (12064); reused by W13 / W2 bufs
#define U2_H1   20768          // h1: 64 x 116 = 7424
#define U2_TOT  28192
#define SMEM_BYTES (U2_TOT * 8)    // 225536 bytes

// layer-1 double buffers alias [0..19008): per buffer [x 64x36 | w 200x36]
#define BUFSZ   9504
#define BX      0
#define BW      2304

// Pre-split interleaved weight planes in global (written once per launch).
// Pads (rows/words beyond real dims) are zero.
__device__ uint2 gW1u [200*384];   // pitch 384 (768 k)
__device__ uint2 gW12u[104*116];   // pitch 116; rows>=100 zero, words>=100 zero
__device__ uint2 gW13u[104*68];    // pitch 68;  rows>=100 zero, words>=50 zero
__device__ uint2 gW2u [512*68];    // pitch 68;  words>=50 zero

// Global accumulators
__device__ double g_mu[HDIM];
__device__ double g_S;
__device__ double g_diff;
__device__ double g_part0;

__global__ void zero_kernel() {
    int t = threadIdx.x;
    if (t < HDIM) g_mu[t] = 0.0;
    if (t == 0) { g_S = 0.0; g_diff = 0.0; g_part0 = 0.0; }
}

// ---------------- bf16 split helpers ----------------
__device__ __forceinline__ void split2(float a, float b, unsigned &hi, unsigned &lo) {
    __nv_bfloat16 ha = __float2bfloat16_rn(a);
    __nv_bfloat16 hb = __float2bfloat16_rn(b);
    float la = a - __bfloat162float(ha);
    float lb = b - __bfloat162float(hb);
    __nv_bfloat162 hp; hp.x = ha; hp.y = hb;
    __nv_bfloat162 lp; lp.x = __float2bfloat16_rn(la); lp.y = __float2bfloat16_rn(lb);
    hi = *reinterpret_cast<unsigned*>(&hp);
    lo = *reinterpret_cast<unsigned*>(&lp);
}

// One-time weight pre-split into interleaved uint2 planes (pads zeroed).
__global__ void presplit_kernel(const float* __restrict__ W1,  const float* __restrict__ W12,
                                const float* __restrict__ W13, const float* __restrict__ W2)
{
    int i = blockIdx.x * 256 + threadIdx.x;
    if (i < 76800) {                                   // W1 [200][384]
        int c = i / 384, w = i % 384;
        uint2 u; split2(W1[c*DIN + 2*w], W1[c*DIN + 2*w + 1], u.x, u.y);
        gW1u[i] = u;
    } else if (i < 88864) {                            // W12 [104][116]
        int j = i - 76800; int c = j / 116, w = j % 116;
        float a = 0.f, b = 0.f;
        if (c < D2 && w < 100) { a = W12[c*D1 + 2*w]; b = W12[c*D1 + 2*w + 1]; }
        uint2 u; split2(a, b, u.x, u.y);
        gW12u[j] = u;
    } else if (i < 95936) {                            // W13 [104][68]
        int j = i - 88864; int c = j / 68, w = j % 68;
        float a = 0.f, b = 0.f;
        if (c < D3 && w < 50) { a = W13[c*D2 + 2*w]; b = W13[c*D2 + 2*w + 1]; }
        uint2 u; split2(a, b, u.x, u.y);
        gW13u[j] = u;
    } else if (i < 130752) {                           // W2 [512][68]
        int j = i - 95936; int c = j / 68, w = j % 68;
        float a = 0.f, b = 0.f;
        if (w < 50) { a = W2[c*D3 + 2*w]; b = W2[c*D3 + 2*w + 1]; }
        uint2 u; split2(a, b, u.x, u.y);
        gW2u[j] = u;
    }
}

// ---------------- cp.async helpers ----------------
__device__ __forceinline__ void cp16(uint2* smem_dst, const uint2* gsrc) {
    unsigned saddr = (unsigned)__cvta_generic_to_shared(smem_dst);
    asm volatile("cp.async.ca.shared.global [%0], [%1], 16;" :: "r"(saddr), "l"(gsrc));
}
#define CP_COMMIT() asm volatile("cp.async.commit_group;")
#define CP_WAIT0()  asm volatile("cp.async.wait_group 0;" ::: "memory")

// flat plane copy (count uint2, even, both src/dst 16B aligned)
__device__ __forceinline__ void stage_flat(uint2* dst, const uint2* src, int pairs, int tid) {
    for (int i = tid; i < pairs; i += TH)
        cp16(&dst[i*2], &src[i*2]);
}

__device__ __forceinline__ void mma16(float* c,
                                      unsigned a0, unsigned a1, unsigned a2, unsigned a3,
                                      unsigned b0, unsigned b1) {
    asm volatile(
        "mma.sync.aligned.m16n8k16.row.col.f32.bf16.bf16.f32 "
        "{%0,%1,%2,%3}, {%4,%5,%6,%7}, {%8,%9}, {%0,%1,%2,%3};"
        : "+f"(c[0]), "+f"(c[1]), "+f"(c[2]), "+f"(c[3])
        : "r"(a0), "r"(a1), "r"(a2), "r"(a3), "r"(b0), "r"(b1));
}

// Warp GEMM on interleaved planes: per k-step 4 A LDS.64 + 2 B LDS.64/tile + 3 MMA/tile.
template<int NT, int LDA, int LDB>
__device__ __forceinline__ void gemm_i(float (*acc)[4],
                                       const uint2* __restrict__ A,
                                       const uint2* __restrict__ B,
                                       int ksteps, int g, int tg)
{
    for (int ks = 0; ks < ksteps; ks++) {
        const int w0 = ks * 8;
        uint2 a0 = A[ g      * LDA + w0 + tg    ];
        uint2 a1 = A[(g + 8) * LDA + w0 + tg    ];
        uint2 a2 = A[ g      * LDA + w0 + tg + 4];
        uint2 a3 = A[(g + 8) * LDA + w0 + tg + 4];
        #pragma unroll
        for (int t = 0; t < NT; t++) {
            const int bo = (t * 8 + g) * LDB + w0 + tg;
            uint2 b0 = B[bo], b1 = B[bo + 4];
            mma16(acc[t], a0.x, a1.x, a2.x, a3.x, b0.x, b1.x);
            mma16(acc[t], a0.x, a1.x, a2.x, a3.x, b0.y, b1.y);
            mma16(acc[t], a0.y, a1.y, a2.y, a3.y, b0.x, b1.x);
        }
    }
}

template<int NT>
__device__ __forceinline__ void init_bias(float (*acc)[4], const float* __restrict__ bias,
                                          int n0, int tg, int nvalid)
{
    #pragma unroll
    for (int t = 0; t < NT; t++) {
        int c = n0 + t * 8 + tg * 2;
        float2 bv = make_float2(0.f, 0.f);
        if (c < nvalid) bv = *(const float2*)&bias[c];
        acc[t][0] = bv.x; acc[t][2] = bv.x;
        acc[t][1] = bv.y; acc[t][3] = bv.y;
    }
}

// relu + bf16 split + pack: cols (c,c+1) -> next layer's k-pair uint2 at word c/2.
template<int NT>
__device__ __forceinline__ void store_relu_i(float (*acc)[4], uint2* __restrict__ H,
                                             int ldw, int m0, int n0,
                                             int g, int tg, int nvalid)
{
    #pragma unroll
    for (int t = 0; t < NT; t++) {
        int c = n0 + t * 8 + tg * 2;
        if (c < nvalid) {
            uint2 u0, u1;
            split2(fmaxf(acc[t][0], 0.f), fmaxf(acc[t][1], 0.f), u0.x, u0.y);
            split2(fmaxf(acc[t][2], 0.f), fmaxf(acc[t][3], 0.f), u1.x, u1.y);
            H[(m0 + g    ) * ldw + (c >> 1)] = u0;
            H[(m0 + g + 8) * ldw + (c >> 1)] = u1;
        }
    }
}

// x chunk global load (chunk cc covers k [cc*64, cc*64+64))
__device__ __forceinline__ float4 ldx(const float* __restrict__ input,
                                      const float* __restrict__ h,
                                      int row0, int cc, int i)
{
    int r = i >> 4, q = i & 15;
    int k0 = cc * 64;
    const float* src; int ss;
    if (k0 < PDIM) { src = input + (size_t)row0 * PDIM + k0; ss = PDIM; }
    else           { src = h     + (size_t)row0 * HDIM + (k0 - PDIM); ss = HDIM; }
    return *(const float4*)(src + (size_t)r * ss + q * 4);
}
// store x as interleaved: one uint4 = words (2q, 2q+1) both planes
__device__ __forceinline__ void stx(uint2* x, int i, float4 v) {
    int r = i >> 4, q = i & 15;
    uint4 u;
    split2(v.x, v.y, u.x, u.y);
    split2(v.z, v.w, u.z, u.w);
    *(uint4*)&x[r * 36 + q * 2] = u;
}

__global__ __launch_bounds__(TH, 1)
void mlp_kernel(const float* __restrict__ input,
                const float* __restrict__ h,
                const float* __restrict__ b1,  const float* __restrict__ b12,
                const float* __restrict__ b13, const float* __restrict__ b2,
                float* __restrict__ out)
{
    extern __shared__ uint2 smem[];
    uint2* h2S = smem + U2_H2;   // 64 x 68
    uint2* h3S = smem + U2_H3;   // 64 x 68
    uint2* wS  = smem + U2_W;    // staging
    uint2* h1S = smem + U2_H1;   // 64 x 116

    const int tid  = threadIdx.x;
    const int lane = tid & 31;
    const int wid  = tid >> 5;     // 0..15
    const int g    = lane >> 2;
    const int tg   = lane & 3;
    const int rowg = wid >> 2;     // 0..3
    const int nq   = wid & 3;      // n-quarter
    const int m0   = rowg * 16;
    const int row0 = blockIdx.x * ROWS;

    float acc[7][4];

    const int L1_N0[4]  = {0, 56, 104, 152};   // 25 tiles -> {7,6,6,6}
    const int L23_N0[4] = {0, 32, 56, 80};     // 13 tiles -> {4,3,3,3}

    // ===================== Layer 1: [64x768] @ W1^T -> relu [64x200] =====================
    if (nq == 0) init_bias<7>(acc, b1, 0, tg, D1);
    else         init_bias<6>(acc, b1, L1_N0[nq], tg, D1);

    // prologue: stage chunk 0 into buf0
    {
        uint2* buf = smem;
        for (int i = tid; i < 200 * 16; i += TH) {
            int c = i >> 4, q = i & 15;
            cp16(&buf[BW + c*36 + q*2], &gW1u[c*384 + q*2]);
        }
        CP_COMMIT();
        float4 xv0 = ldx(input, h, row0, 0, tid);
        float4 xv1 = ldx(input, h, row0, 0, tid + TH);
        stx(buf + BX, tid,      xv0);
        stx(buf + BX, tid + TH, xv1);
        CP_WAIT0();
    }
    __syncthreads();

    #pragma unroll 1
    for (int ch = 0; ch < 12; ch++) {
        uint2* cur = smem + (ch & 1) * BUFSZ;
        uint2* nxt = smem + ((ch + 1) & 1) * BUFSZ;
        float4 xv0, xv1;
        if (ch < 11) {
            for (int i = tid; i < 200 * 16; i += TH) {
                int c = i >> 4, q = i & 15;
                cp16(&nxt[BW + c*36 + q*2], &gW1u[c*384 + (ch+1)*32 + q*2]);
            }
            CP_COMMIT();
            xv0 = ldx(input, h, row0, ch + 1, tid);
            xv1 = ldx(input, h, row0, ch + 1, tid + TH);
        }
        {
            const uint2* A = cur + BX + m0 * 36;
            int o = L1_N0[nq] * 36;
            if (nq == 0) gemm_i<7, 36, 36>(acc, A, cur + BW, 4, g, tg);
            else         gemm_i<6, 36, 36>(acc, A, cur + BW + o, 4, g, tg);
        }
        if (ch < 11) {
            stx(nxt + BX, tid,      xv0);
            stx(nxt + BX, tid + TH, xv1);
            CP_WAIT0();
        }
        __syncthreads();
    }

    // h1 store (region above buffers) + stage W12 flat + zero pads; single barrier
    if (nq == 0) store_relu_i<7>(acc, h1S, 116, m0, 0, g, tg, D1);
    else         store_relu_i<6>(acc, h1S, 116, m0, L1_N0[nq], g, tg, D1);
    {
        stage_flat(wS, gW12u, 6032, tid);      // 104x116 uint2
        CP_COMMIT();
        // zero pads: h1 words 100..103; h2/h3 words 50..55 (buffer region dead now)
        for (int i = tid; i < 64 * 4; i += TH) {
            int r = i >> 2, w = 100 + (i & 3);
            h1S[r * 116 + w] = make_uint2(0u, 0u);
        }
        for (int i = tid; i < 64 * 6; i += TH) {
            int r = i / 6, w = 50 + (i % 6);
            h2S[r * 68 + w] = make_uint2(0u, 0u);
            h3S[r * 68 + w] = make_uint2(0u, 0u);
        }
        CP_WAIT0();
    }
    __syncthreads();

    // ===================== Layer 2: [64x200] @ W12^T -> relu [64x100] =====================
    {
        const uint2* A = h1S + m0 * 116;
        int o = L23_N0[nq] * 116;
        if (nq == 0) {
            init_bias<4>(acc, b12, 0, tg, D2);
            gemm_i<4, 116, 116>(acc, A, wS + o, 13, g, tg);
            store_relu_i<4>(acc, h2S, 68, m0, 0, g, tg, D2);
        } else {
            init_bias<3>(acc, b12, L23_N0[nq], tg, D2);
            gemm_i<3, 116, 116>(acc, A, wS + o, 13, g, tg);
            store_relu_i<3>(acc, h2S, 68, m0, L23_N0[nq], g, tg, D2);
        }
    }
    __syncthreads();

    // stage W13 flat (104x68 uint2)
    stage_flat(wS, gW13u, 3536, tid);
    CP_COMMIT(); CP_WAIT0();
    __syncthreads();

    // ===================== Layer 3: [64x100] @ W13^T -> relu [64x100] =====================
    {
        const uint2* A = h2S + m0 * 68;
        int o = L23_N0[nq] * 68;
        if (nq == 0) {
            init_bias<4>(acc, b13, 0, tg, D3);
            gemm_i<4, 68, 68>(acc, A, wS + o, 7, g, tg);
            store_relu_i<4>(acc, h3S, 68, m0, 0, g, tg, D3);
        } else {
            init_bias<3>(acc, b13, L23_N0[nq], tg, D3);
            gemm_i<3, 68, 68>(acc, A, wS + o, 7, g, tg);
            store_relu_i<3>(acc, h3S, 68, m0, L23_N0[nq], g, tg, D3);
        }
    }
    __syncthreads();

    // ===================== Layer 4: 8 chunks of 64 cols, double-buffered ==================
    stage_flat(wS, gW2u, 2176, tid);           // chunk 0: 64x68 uint2
    CP_COMMIT(); CP_WAIT0();
    __syncthreads();

    float dd = 0.f;
    #pragma unroll 1
    for (int c4 = 0; c4 < 8; c4++) {
        uint2* cur = wS + (c4 & 1) * 4352;
        uint2* nxt = wS + ((c4 + 1) & 1) * 4352;
        if (c4 < 7) {
            stage_flat(nxt, gW2u + (c4 + 1) * 64 * 68, 2176, tid);
            CP_COMMIT();
        }
        init_bias<2>(acc, b2, c4 * 64 + nq * 16, tg, DOUT);
        gemm_i<2, 68, 68>(acc, h3S + m0 * 68, cur + nq * 16 * 68, 7, g, tg);

        #pragma unroll
        for (int t = 0; t < 2; t++) {
            int c  = c4 * 64 + nq * 16 + t * 8 + tg * 2;
            int r1 = row0 + m0 + g;
            int r2 = r1 + 8;
            float2 v0 = make_float2(acc[t][0], acc[t][1]);
            float2 v1 = make_float2(acc[t][2], acc[t][3]);
            *(float2*)&out[(size_t)r1 * PDIM + c] = v0;
            *(float2*)&out[(size_t)r2 * PDIM + c] = v1;
            if (r1 < NROWS - 1) {
                float2 nx = *(const float2*)&input[(size_t)(r1 + 1) * PDIM + c];
                float d0 = v0.x - nx.x, d1 = v0.y - nx.y;
                dd += d0 * d0 + d1 * d1;
            }
            if (r2 < NROWS - 1) {
                float2 nx = *(const float2*)&input[(size_t)(r2 + 1) * PDIM + c];
                float d0 = v1.x - nx.x, d1 = v1.y - nx.y;
                dd += d0 * d0 + d1 * d1;
            }
        }
        if (c4 < 7) CP_WAIT0();
        __syncthreads();
    }

    // reduce dd -> g_part0
    #pragma unroll
    for (int off = 16; off > 0; off >>= 1)
        dd += __shfl_down_sync(0xFFFFFFFFu, dd, off);
    __shared__ float wdd[16];
    if (lane == 0) wdd[wid] = dd;
    __syncthreads();
    if (tid == 0) {
        float s = 0.f;
        #pragma unroll
        for (int w = 0; w < 16; w++) s += wdd[w];
        atomicAdd(&g_part0, (double)s);
    }
}

// h statistics: column sums (mu), sum of squares (S), total variation (diff)
__global__ __launch_bounds__(HDIM)
void hred_kernel(const float* __restrict__ h)
{
    const int c  = threadIdx.x;
    const int r0 = blockIdx.x * 256;
    float prev = (r0 > 0) ? h[(size_t)(r0 - 1) * HDIM + c] : 0.f;
    float cs = 0.f, sq = 0.f, df = 0.f;
    #pragma unroll 4
    for (int i = 0; i < 256; i++) {
        float v = h[(size_t)(r0 + i) * HDIM + c];
        cs += v;
        sq += v * v;
        if (r0 + i > 0) df += fabsf(v - prev);
        prev = v;
    }
    atomicAdd(&g_mu[c], (double)cs);

    #pragma unroll
    for (int off = 16; off > 0; off >>= 1) {
        sq += __shfl_down_sync(0xFFFFFFFFu, sq, off);
        df += __shfl_down_sync(0xFFFFFFFFu, df, off);
    }
    __shared__ float wsq[8], wdf[8];
    int tx = c & 31, ty = c >> 5;
    if (tx == 0) { wsq[ty] = sq; wdf[ty] = df; }
    __syncthreads();
    if (c == 0) {
        float s1 = 0.f, s2 = 0.f;
        #pragma unroll
        for (int w = 0; w < 8; w++) { s1 += wsq[w]; s2 += wdf[w]; }
        atomicAdd(&g_S, (double)s1);
        atomicAdd(&g_diff, (double)s2);
    }
}

__global__ void finalize_kernel(float* __restrict__ out, long long base)
{
    __shared__ double red[HDIM];
    int t = threadIdx.x;
    red[t] = fabs(g_mu[t]);
    __syncthreads();
    for (int s = 128; s > 0; s >>= 1) {
        if (t < s) red[t] += red[t + s];
        __syncthreads();
    }
    if (t == 0) {
        const double Nn = (double)NROWS;
        out[base + 0] = (float)(sqrt(g_part0) / (Nn - 1.0));
        out[base + 1] = (float)(red[0] / Nn / (double)HDIM);
        out[base + 2] = (float)fabs(g_S / Nn / (double)HDIM - 1.0);
        out[base + 3] = (float)(g_diff / (Nn - 1.0) / (double)HDIM);
    }
}

extern "C" void kernel_launch(void* const* d_in, const int* in_sizes, int n_in,
                              void* d_out, int out_size)
{
    const float* input = (const float*)d_in[0];
    const float* h     = (const float*)d_in[1];
    const float* W1    = (const float*)d_in[2];
    const float* b1    = (const float*)d_in[3];
    const float* W12   = (const float*)d_in[4];
    const float* b12   = (const float*)d_in[5];
    const float* W13   = (const float*)d_in[6];
    const float* b13   = (const float*)d_in[7];
    const float* W2    = (const float*)d_in[8];
    const float* b2    = (const float*)d_in[9];
    float* out = (float*)d_out;

    cudaFuncSetAttribute(mlp_kernel, cudaFuncAttributeMaxDynamicSharedMemorySize, SMEM_BYTES);

    zero_kernel<<<1, 256>>>();
    presplit_kernel<<<511, 256>>>(W1, W12, W13, W2);
    hred_kernel<<<NROWS / 256, HDIM>>>(h);
    mlp_kernel<<<NROWS / ROWS, TH, SMEM_BYTES>>>(input, h, b1, b12, b13, b2, out);
    finalize_kernel<<<1, HDIM>>>(out, (long long)out_size - 4);
}

// round 16
// speedup vs baseline: 1.4743x; 1.4743x over previous
#include <cuda_runtime.h>
#include <cuda_bf16.h>
#include <math.h>

// Problem constants
#define NROWS 65536
#define PDIM  512
#define HDIM  256
#define DIN   768
#define D1    200
#define D2    100
#define D3    100
#define DOUT  512

#define ROWS  64      // rows per block
#define TH    768     // threads per block (24 warps: 4 row-groups x 6 n-slices)

// ---- SMEM layout in u32 words.  All matrix data = packed bf16x2 hi/lo planes.
// Pitches mod 32 in {4,12,28} -> conflict-free LDS.32 fragment loads.
// Lifetimes: layer-1 double buffers (0..38016) die before h2/h3/W-staging live.
#define SM_H2    0            // h2: 2 planes x 64x60
#define SM_H3    7680         // h3: 2 planes x 64x60
#define SM_W     15360        // weight staging area (26624 words)
#define SM_H1    41984        // h1: 2 planes x 64x108
#define SM_TOT   55808        // words
#define SMEM_BYTES (SM_TOT * 4)   // 223232 bytes

// layer-1 double buffers: [xHi 2304 | xLo 2304 | wHi 7200 | wLo 7200] = 19008 words
#define BUFSZ    19008
#define BXH      0
#define BXL      2304
#define BWH      4608
#define BWL      11808

// Pre-split weight planes in global (written once per launch by presplit_kernel)
__device__ unsigned gW1 [2][200*384];   // k words 0..383 (768 k), no pad
__device__ unsigned gW12[2][104*104];   // rows 100..103 zero, words 100..103 zero
__device__ unsigned gW13[2][104*56];    // rows 100..103 zero, words 50..55 zero
__device__ unsigned gW2 [2][512*56];    // words 50..55 zero

// Global accumulators
__device__ double g_mu[HDIM];
__device__ double g_S;
__device__ double g_diff;
__device__ double g_part0;

__global__ void zero_kernel() {
    int t = threadIdx.x;
    if (t < HDIM) g_mu[t] = 0.0;
    if (t == 0) { g_S = 0.0; g_diff = 0.0; g_part0 = 0.0; }
}

// ---------------- bf16 split helpers ----------------
__device__ __forceinline__ void split2(float a, float b, unsigned &hi, unsigned &lo) {
    __nv_bfloat16 ha = __float2bfloat16_rn(a);
    __nv_bfloat16 hb = __float2bfloat16_rn(b);
    float la = a - __bfloat162float(ha);
    float lb = b - __bfloat162float(hb);
    __nv_bfloat162 hp; hp.x = ha; hp.y = hb;
    __nv_bfloat162 lp; lp.x = __float2bfloat16_rn(la); lp.y = __float2bfloat16_rn(lb);
    hi = *reinterpret_cast<unsigned*>(&hp);
    lo = *reinterpret_cast<unsigned*>(&lp);
}
__device__ __forceinline__ void split4w(float4 v, uint2 &h2v, uint2 &l2v) {
    split2(v.x, v.y, h2v.x, l2v.x);
    split2(v.z, v.w, h2v.y, l2v.y);
}

// One-time weight pre-split: fp32 -> packed bf16x2 hi/lo planes with pad baked in.
__global__ void presplit_kernel(const float* __restrict__ W1,  const float* __restrict__ W12,
                                const float* __restrict__ W13, const float* __restrict__ W2)
{
    int i = blockIdx.x * 256 + threadIdx.x;
    if (i < 76800) {                                 // W1: [200][384]
        int c = i / 384, w = i % 384;
        split2(W1[c*DIN + 2*w], W1[c*DIN + 2*w + 1], gW1[0][i], gW1[1][i]);
    } else if (i < 87616) {                          // W12: [104][104]
        int j = i - 76800; int c = j / 104, w = j % 104;
        float a = 0.f, b = 0.f;
        if (c < D2 && w < 100) { a = W12[c*D1 + 2*w]; b = W12[c*D1 + 2*w + 1]; }
        split2(a, b, gW12[0][j], gW12[1][j]);
    } else if (i < 93440) {                          // W13: [104][56]
        int j = i - 87616; int c = j / 56, w = j % 56;
        float a = 0.f, b = 0.f;
        if (c < D3 && w < 50) { a = W13[c*D2 + 2*w]; b = W13[c*D2 + 2*w + 1]; }
        split2(a, b, gW13[0][j], gW13[1][j]);
    } else if (i < 122112) {                         // W2: [512][56]
        int j = i - 93440; int c = j / 56, w = j % 56;
        float a = 0.f, b = 0.f;
        if (w < 50) { a = W2[c*D3 + 2*w]; b = W2[c*D3 + 2*w + 1]; }
        split2(a, b, gW2[0][j], gW2[1][j]);
    }
}

// ---------------- cp.async helpers ----------------
__device__ __forceinline__ void cp16(unsigned* smem_dst, const unsigned* gsrc) {
    unsigned saddr = (unsigned)__cvta_generic_to_shared(smem_dst);
    asm volatile("cp.async.ca.shared.global [%0], [%1], 16;" :: "r"(saddr), "l"(gsrc));
}
#define CP_COMMIT() asm volatile("cp.async.commit_group;")
#define CP_WAIT0()  asm volatile("cp.async.wait_group 0;" ::: "memory")

// flat plane copy via cp.async: rows x (qwords*4) words, dst pitch / src pitch
__device__ __forceinline__ void stage_flat(unsigned* dHi, unsigned* dLo,
                                           const unsigned* sHi, const unsigned* sLo,
                                           int rows, int qwords, int dpitch, int spitch,
                                           int tid)
{
    for (int i = tid; i < rows * qwords; i += TH) {
        int c = i / qwords, q = i % qwords;
        cp16(&dHi[c*dpitch + q*4], &sHi[c*spitch + q*4]);
        cp16(&dLo[c*dpitch + q*4], &sLo[c*spitch + q*4]);
    }
}

__device__ __forceinline__ void mma16(float* c,
                                      unsigned a0, unsigned a1, unsigned a2, unsigned a3,
                                      unsigned b0, unsigned b1) {
    asm volatile(
        "mma.sync.aligned.m16n8k16.row.col.f32.bf16.bf16.f32 "
        "{%0,%1,%2,%3}, {%4,%5,%6,%7}, {%8,%9}, {%0,%1,%2,%3};"
        : "+f"(c[0]), "+f"(c[1]), "+f"(c[2]), "+f"(c[3])
        : "r"(a0), "r"(a1), "r"(a2), "r"(a3), "r"(b0), "r"(b1));
}

// Warp GEMM, pre-split planes: inner work = LDS.32 + MMA only (3-term split).
template<int NT, int LDA, int LDB>
__device__ __forceinline__ void gemm_bf(float (*acc)[4],
                                        const unsigned* __restrict__ Ah,
                                        const unsigned* __restrict__ Al,
                                        const unsigned* __restrict__ Bh,
                                        const unsigned* __restrict__ Bl,
                                        int ksteps, int g, int tg)
{
    for (int ks = 0; ks < ksteps; ks++) {
        const int w0 = ks * 8;
        const int oA0 =  g      * LDA + w0 + tg;
        const int oA1 = (g + 8) * LDA + w0 + tg;
        unsigned ah0 = Ah[oA0], ah1 = Ah[oA1], ah2 = Ah[oA0 + 4], ah3 = Ah[oA1 + 4];
        unsigned al0 = Al[oA0], al1 = Al[oA1], al2 = Al[oA0 + 4], al3 = Al[oA1 + 4];
        #pragma unroll
        for (int t = 0; t < NT; t++) {
            const int bo = (t * 8 + g) * LDB + w0 + tg;
            unsigned bh0 = Bh[bo], bh1 = Bh[bo + 4];
            unsigned bl0 = Bl[bo], bl1 = Bl[bo + 4];
            mma16(acc[t], ah0, ah1, ah2, ah3, bh0, bh1);
            mma16(acc[t], ah0, ah1, ah2, ah3, bl0, bl1);
            mma16(acc[t], al0, al1, al2, al3, bh0, bh1);
        }
    }
}

template<int NT>
__device__ __forceinline__ void init_bias(float (*acc)[4], const float* __restrict__ bias,
                                          int n0, int tg, int nvalid)
{
    #pragma unroll
    for (int t = 0; t < NT; t++) {
        int c = n0 + t * 8 + tg * 2;
        float2 bv = make_float2(0.f, 0.f);
        if (c < nvalid) bv = *(const float2*)&bias[c];
        acc[t][0] = bv.x; acc[t][2] = bv.x;
        acc[t][1] = bv.y; acc[t][3] = bv.y;
    }
}

// relu + bf16 split + pack: cols (c, c+1) become next layer's k-pair word c/2.
template<int NT>
__device__ __forceinline__ void store_relu_bf(float (*acc)[4],
                                              unsigned* __restrict__ Hh,
                                              unsigned* __restrict__ Hl,
                                              int ldw, int m0, int n0,
                                              int g, int tg, int nvalid)
{
    #pragma unroll
    for (int t = 0; t < NT; t++) {
        int c = n0 + t * 8 + tg * 2;
        if (c < nvalid) {
            unsigned h0, l0, h1, l1;
            split2(fmaxf(acc[t][0], 0.f), fmaxf(acc[t][1], 0.f), h0, l0);
            split2(fmaxf(acc[t][2], 0.f), fmaxf(acc[t][3], 0.f), h1, l1);
            int o0 = (m0 + g) * ldw + (c >> 1);
            int o1 = (m0 + g + 8) * ldw + (c >> 1);
            Hh[o0] = h0; Hl[o0] = l0;
            Hh[o1] = h1; Hl[o1] = l1;
        }
    }
}

// x chunk global load (chunk cc covers k [cc*64, cc*64+64))
__device__ __forceinline__ float4 ldx(const float* __restrict__ input,
                                      const float* __restrict__ h,
                                      int row0, int cc, int i)
{
    int r = i >> 4, q = i & 15;
    int k0 = cc * 64;
    const float* src; int ss;
    if (k0 < PDIM) { src = input + (size_t)row0 * PDIM + k0; ss = PDIM; }
    else           { src = h     + (size_t)row0 * HDIM + (k0 - PDIM); ss = HDIM; }
    return *(const float4*)(src + (size_t)r * ss + q * 4);
}
__device__ __forceinline__ void stx(unsigned* xHi, unsigned* xLo, int i, float4 v) {
    int r = i >> 4, q = i & 15;
    uint2 hw, lw; split4w(v, hw, lw);
    *(uint2*)&xHi[r * 36 + q * 2] = hw;
    *(uint2*)&xLo[r * 36 + q * 2] = lw;
}

__global__ __launch_bounds__(TH, 1)
void mlp_kernel(const float* __restrict__ input,
                const float* __restrict__ h,
                const float* __restrict__ b1,  const float* __restrict__ b12,
                const float* __restrict__ b13, const float* __restrict__ b2,
                float* __restrict__ out)
{
    extern __shared__ unsigned smem[];
    unsigned* h2Hi = smem + SM_H2;  unsigned* h2Lo = h2Hi + 3840;   // 64x60
    unsigned* h3Hi = smem + SM_H3;  unsigned* h3Lo = h3Hi + 3840;   // 64x60
    unsigned* h1Hi = smem + SM_H1;  unsigned* h1Lo = h1Hi + 6912;   // 64x108

    const int tid  = threadIdx.x;
    const int lane = tid & 31;
    const int wid  = tid >> 5;     // 0..23
    const int g    = lane >> 2;
    const int tg   = lane & 3;
    const int rowg = wid / 6;      // 0..3
    const int nq   = wid % 6;      // n-slice 0..5
    const int m0   = rowg * 16;
    const int row0 = blockIdx.x * ROWS;

    float acc[5][4];

    // L1: 25 tiles -> {5,4,4,4,4,4}; L2/L3: 13 -> {3,2,2,2,2,2}; L4 (per 64-chunk): 8 -> {2,2,1,1,1,1}
    const int L1_N0[6]  = {0, 40, 72, 104, 136, 168};
    const int L23_N0[6] = {0, 24, 40, 56, 72, 88};
    const int L4_N0[6]  = {0, 16, 32, 40, 48, 56};

    // ===================== Layer 1: [64x768] @ W1^T -> relu [64x200] =====================
    if (nq == 0) init_bias<5>(acc, b1, 0, tg, D1);
    else         init_bias<4>(acc, b1, L1_N0[nq], tg, D1);

    // prologue: stage chunk 0 into buf0
    {
        unsigned* buf = smem;   // buf0
        for (int i = tid; i < 200 * 8; i += TH) {
            int c = i >> 3, q = i & 7;
            cp16(&buf[BWH + c*36 + q*4], &gW1[0][c*384 + q*4]);
            cp16(&buf[BWL + c*36 + q*4], &gW1[1][c*384 + q*4]);
        }
        CP_COMMIT();
        float4 xv0 = ldx(input, h, row0, 0, tid);
        stx(buf + BXH, buf + BXL, tid, xv0);
        if (tid + TH < 1024) {
            float4 xv1 = ldx(input, h, row0, 0, tid + TH);
            stx(buf + BXH, buf + BXL, tid + TH, xv1);
        }
        CP_WAIT0();
    }
    __syncthreads();

    #pragma unroll 1
    for (int ch = 0; ch < 12; ch++) {
        unsigned* cur = smem + (ch & 1) * BUFSZ;
        unsigned* nxt = smem + ((ch + 1) & 1) * BUFSZ;
        float4 xv0, xv1;
        if (ch < 11) {
            // issue next weight chunk + load next x chunk (overlaps compute below)
            for (int i = tid; i < 200 * 8; i += TH) {
                int c = i >> 3, q = i & 7;
                cp16(&nxt[BWH + c*36 + q*4], &gW1[0][c*384 + (ch+1)*32 + q*4]);
                cp16(&nxt[BWL + c*36 + q*4], &gW1[1][c*384 + (ch+1)*32 + q*4]);
            }
            CP_COMMIT();
            xv0 = ldx(input, h, row0, ch + 1, tid);
            if (tid + TH < 1024) xv1 = ldx(input, h, row0, ch + 1, tid + TH);
        }
        // compute chunk ch
        {
            const unsigned* Ah = cur + BXH + m0 * 36;
            const unsigned* Al = cur + BXL + m0 * 36;
            int o = L1_N0[nq] * 36;
            if (nq == 0) gemm_bf<5, 36, 36>(acc, Ah, Al, cur + BWH, cur + BWL, 4, g, tg);
            else         gemm_bf<4, 36, 36>(acc, Ah, Al, cur + BWH + o, cur + BWL + o, 4, g, tg);
        }
        if (ch < 11) {
            stx(nxt + BXH, nxt + BXL, tid, xv0);
            if (tid + TH < 1024) stx(nxt + BXH, nxt + BXL, tid + TH, xv1);
            CP_WAIT0();
        }
        __syncthreads();
    }

    // h1 store (region untouched by buffers) + pads + stage W12; single barrier
    if (nq == 0) store_relu_bf<5>(acc, h1Hi, h1Lo, 108, m0, 0, g, tg, D1);
    else         store_relu_bf<4>(acc, h1Hi, h1Lo, 108, m0, L1_N0[nq], g, tg, D1);
    {
        unsigned* wHi = smem + SM_W;          // W12 plane pitch 108 (11232 words)
        unsigned* wLo = wHi + 11232;
        stage_flat(wHi, wLo, gW12[0], gW12[1], 104, 26, 108, 104, tid);
        CP_COMMIT();
        // zero pads: h1 words 100..103, h2/h3 words 50..55 (buffer space now dead)
        for (int i = tid; i < 64 * 4; i += TH) {
            int r = i >> 2, w = 100 + (i & 3);
            h1Hi[r * 108 + w] = 0; h1Lo[r * 108 + w] = 0;
        }
        for (int i = tid; i < 64 * 6; i += TH) {
            int r = i / 6, w = 50 + (i % 6);
            h2Hi[r * 60 + w] = 0; h2Lo[r * 60 + w] = 0;
            h3Hi[r * 60 + w] = 0; h3Lo[r * 60 + w] = 0;
        }
        CP_WAIT0();
    }
    __syncthreads();

    // ===================== Layer 2: [64x200] @ W12^T -> relu [64x100] =====================
    {
        unsigned* wHi = smem + SM_W; unsigned* wLo = wHi + 11232;
        const unsigned* Ah = h1Hi + m0 * 108;
        const unsigned* Al = h1Lo + m0 * 108;
        int o = L23_N0[nq] * 108;
        if (nq == 0) {
            init_bias<3>(acc, b12, 0, tg, D2);
            gemm_bf<3, 108, 108>(acc, Ah, Al, wHi + o, wLo + o, 13, g, tg);
            store_relu_bf<3>(acc, h2Hi, h2Lo, 60, m0, 0, g, tg, D2);
        } else {
            init_bias<2>(acc, b12, L23_N0[nq], tg, D2);
            gemm_bf<2, 108, 108>(acc, Ah, Al, wHi + o, wLo + o, 13, g, tg);
            store_relu_bf<2>(acc, h2Hi, h2Lo, 60, m0, L23_N0[nq], g, tg, D2);
        }
    }
    __syncthreads();

    // stage W13 (pitch 60, 6240 words/plane)
    {
        unsigned* wHi = smem + SM_W; unsigned* wLo = wHi + 6240;
        stage_flat(wHi, wLo, gW13[0], gW13[1], 104, 14, 60, 56, tid);
        CP_COMMIT(); CP_WAIT0();
    }
    __syncthreads();

    // ===================== Layer 3: [64x100] @ W13^T -> relu [64x100] =====================
    {
        unsigned* wHi = smem + SM_W; unsigned* wLo = wHi + 6240;
        const unsigned* Ah = h2Hi + m0 * 60;
        const unsigned* Al = h2Lo + m0 * 60;
        int o = L23_N0[nq] * 60;
        if (nq == 0) {
            init_bias<3>(acc, b13, 0, tg, D3);
            gemm_bf<3, 60, 60>(acc, Ah, Al, wHi + o, wLo + o, 7, g, tg);
            store_relu_bf<3>(acc, h3Hi, h3Lo, 60, m0, 0, g, tg, D3);
        } else {
            init_bias<2>(acc, b13, L23_N0[nq], tg, D3);
            gemm_bf<2, 60, 60>(acc, Ah, Al, wHi + o, wLo + o, 7, g, tg);
            store_relu_bf<2>(acc, h3Hi, h3Lo, 60, m0, L23_N0[nq], g, tg, D3);
        }
    }
    __syncthreads();

    // ===================== Layer 4: 8 chunks of 64 cols, double-buffered ==================
    // W2 chunk buffers: A @ SM_W, B @ SM_W+7680 (each 2 planes x 64x60)
    {
        unsigned* bufA = smem + SM_W;
        stage_flat(bufA, bufA + 3840, gW2[0], gW2[1], 64, 14, 60, 56, tid);
        CP_COMMIT(); CP_WAIT0();
    }
    __syncthreads();

    const int ntL4 = (nq < 2) ? 2 : 1;
    float dd = 0.f;
    #pragma unroll 1
    for (int c4 = 0; c4 < 8; c4++) {
        unsigned* cur = smem + SM_W + (c4 & 1) * 7680;
        unsigned* nxt = smem + SM_W + ((c4 + 1) & 1) * 7680;
        if (c4 < 7) {
            stage_flat(nxt, nxt + 3840, gW2[0] + (c4 + 1) * 64 * 56,
                       gW2[1] + (c4 + 1) * 64 * 56, 64, 14, 60, 56, tid);
            CP_COMMIT();
        }
        {
            const unsigned* Ah = h3Hi + m0 * 60;
            const unsigned* Al = h3Lo + m0 * 60;
            int o = L4_N0[nq] * 60;
            if (nq < 2) {
                init_bias<2>(acc, b2, c4 * 64 + L4_N0[nq], tg, DOUT);
                gemm_bf<2, 60, 60>(acc, Ah, Al, cur + o, cur + 3840 + o, 7, g, tg);
            } else {
                init_bias<1>(acc, b2, c4 * 64 + L4_N0[nq], tg, DOUT);
                gemm_bf<1, 60, 60>(acc, Ah, Al, cur + o, cur + 3840 + o, 7, g, tg);
            }
        }
        for (int t = 0; t < ntL4; t++) {
            int c  = c4 * 64 + L4_N0[nq] + t * 8 + tg * 2;
            int r1 = row0 + m0 + g;
            int r2 = r1 + 8;
            float2 v0 = make_float2(acc[t][0], acc[t][1]);
            float2 v1 = make_float2(acc[t][2], acc[t][3]);
            *(float2*)&out[(size_t)r1 * PDIM + c] = v0;
            *(float2*)&out[(size_t)r2 * PDIM + c] = v1;
            if (r1 < NROWS - 1) {
                float2 nx = *(const float2*)&input[(size_t)(r1 + 1) * PDIM + c];
                float d0 = v0.x - nx.x, d1 = v0.y - nx.y;
                dd += d0 * d0 + d1 * d1;
            }
            if (r2 < NROWS - 1) {
                float2 nx = *(const float2*)&input[(size_t)(r2 + 1) * PDIM + c];
                float d0 = v1.x - nx.x, d1 = v1.y - nx.y;
                dd += d0 * d0 + d1 * d1;
            }
        }
        if (c4 < 7) CP_WAIT0();
        __syncthreads();
    }

    // reduce dd -> g_part0
    #pragma unroll
    for (int off = 16; off > 0; off >>= 1)
        dd += __shfl_down_sync(0xFFFFFFFFu, dd, off);
    __shared__ float wdd[24];
    if (lane == 0) wdd[wid] = dd;
    __syncthreads();
    if (tid == 0) {
        float s = 0.f;
        #pragma unroll
        for (int w = 0; w < 24; w++) s += wdd[w];
        atomicAdd(&g_part0, (double)s);
    }
}

// h statistics: column sums (mu), sum of squares (S), total variation (diff)
__global__ __launch_bounds__(HDIM)
void hred_kernel(const float* __restrict__ h)
{
    const int c  = threadIdx.x;
    const int r0 = blockIdx.x * 256;
    float prev = (r0 > 0) ? h[(size_t)(r0 - 1) * HDIM + c] : 0.f;
    float cs = 0.f, sq = 0.f, df = 0.f;
    #pragma unroll 4
    for (int i = 0; i < 256; i++) {
        float v = h[(size_t)(r0 + i) * HDIM + c];
        cs += v;
        sq += v * v;
        if (r0 + i > 0) df += fabsf(v - prev);
        prev = v;
    }
    atomicAdd(&g_mu[c], (double)cs);

    #pragma unroll
    for (int off = 16; off > 0; off >>= 1) {
        sq += __shfl_down_sync(0xFFFFFFFFu, sq, off);
        df += __shfl_down_sync(0xFFFFFFFFu, df, off);
    }
    __shared__ float wsq[8], wdf[8];
    int tx = c & 31, ty = c >> 5;
    if (tx == 0) { wsq[ty] = sq; wdf[ty] = df; }
    __syncthreads();
    if (c == 0) {
        float s1 = 0.f, s2 = 0.f;
        #pragma unroll
        for (int w = 0; w < 8; w++) { s1 += wsq[w]; s2 += wdf[w]; }
        atomicAdd(&g_S, (double)s1);
        atomicAdd(&g_diff, (double)s2);
    }
}

__global__ void finalize_kernel(float* __restrict__ out, long long base)
{
    __shared__ double red[HDIM];
    int t = threadIdx.x;
    red[t] = fabs(g_mu[t]);
    __syncthreads();
    for (int s = 128; s > 0; s >>= 1) {
        if (t < s) red[t] += red[t + s];
        __syncthreads();
    }
    if (t == 0) {
        const double Nn = (double)NROWS;
        out[base + 0] = (float)(sqrt(g_part0) / (Nn - 1.0));
        out[base + 1] = (float)(red[0] / Nn / (double)HDIM);
        out[base + 2] = (float)fabs(g_S / Nn / (double)HDIM - 1.0);
        out[base + 3] = (float)(g_diff / (Nn - 1.0) / (double)HDIM);
    }
}

extern "C" void kernel_launch(void* const* d_in, const int* in_sizes, int n_in,
                              void* d_out, int out_size)
{
    const float* input = (const float*)d_in[0];
    const float* h     = (const float*)d_in[1];
    const float* W1    = (const float*)d_in[2];
    const float* b1    = (const float*)d_in[3];
    const float* W12   = (const float*)d_in[4];
    const float* b12   = (const float*)d_in[5];
    const float* W13   = (const float*)d_in[6];
    const float* b13   = (const float*)d_in[7];
    const float* W2    = (const float*)d_in[8];
    const float* b2    = (const float*)d_in[9];
    float* out = (float*)d_out;

    cudaFuncSetAttribute(mlp_kernel, cudaFuncAttributeMaxDynamicSharedMemorySize, SMEM_BYTES);

    zero_kernel<<<1, 256>>>();
    presplit_kernel<<<478, 256>>>(W1, W12, W13, W2);
    hred_kernel<<<NROWS / 256, HDIM>>>(h);
    mlp_kernel<<<NROWS / ROWS, TH, SMEM_BYTES>>>(input, h, b1, b12, b13, b2, out);
    finalize_kernel<<<1, HDIM>>>(out, (long long)out_size - 4);
}

// round 17
// speedup vs baseline: 2.0353x; 1.3805x over previous
#include <cuda_runtime.h>
#include <cuda_bf16.h>
#include <cuda_fp16.h>
#include <math.h>

// Problem constants
#define NROWS 65536
#define PDIM  512
#define HDIM  256
#define DIN   768
#define D1    200
#define D2    100
#define D3    100
#define DOUT  512

#define ROWS  64      // rows per block
#define TH    512     // threads per block (16 warps: 4 row-groups x 4 n-quarters)

// ---- SMEM layout in u32 words.
// Layer 1: fp16 single plane, k-chunk 128, double-buffered:
//   per buffer [x 64x68 | W1 200x68] = 17952 words; 2 buffers = 35904 words
// After L1 (buffers dead): h2/h3 (bf16 hi/lo planes), W staging, h1.
#define BUF1SZ   17952
#define BX1      0
#define BW1      4352
#define SM_H2    0            // h2: 2 planes x 64x60 (7680)
#define SM_H3    7680         // h3: 2 planes x 64x60 (7680)
#define SM_W     15360        // weight staging (22464 words max: W12 2x11232)
#define SM_H1    37824        // h1: 2 planes x 64x108 (13824)
#define SM_TOT   51648        // words
#define SMEM_BYTES (SM_TOT * 4)   // 206592 bytes

// Pre-split weights in global (written once per launch by presplit_kernel)
__device__ unsigned gW1h[200*384];      // fp16x2 single plane, pitch 384 (768 k)
__device__ unsigned gW12[2][104*104];   // bf16x2 hi/lo; rows>=100 zero, words>=100 zero
__device__ unsigned gW13[2][104*56];    // rows>=100 zero, words>=50 zero
__device__ unsigned gW2 [2][512*56];    // words>=50 zero

// Global accumulators
__device__ double g_mu[HDIM];
__device__ double g_S;
__device__ double g_diff;
__device__ double g_part0;

__global__ void zero_kernel() {
    int t = threadIdx.x;
    if (t < HDIM) g_mu[t] = 0.0;
    if (t == 0) { g_S = 0.0; g_diff = 0.0; g_part0 = 0.0; }
}

// ---------------- pack / split helpers ----------------
__device__ __forceinline__ unsigned pack_h2(float a, float b) {
    __half2 p = __floats2half2_rn(a, b);
    return *reinterpret_cast<unsigned*>(&p);
}
__device__ __forceinline__ void split2(float a, float b, unsigned &hi, unsigned &lo) {
    __nv_bfloat16 ha = __float2bfloat16_rn(a);
    __nv_bfloat16 hb = __float2bfloat16_rn(b);
    float la = a - __bfloat162float(ha);
    float lb = b - __bfloat162float(hb);
    __nv_bfloat162 hp; hp.x = ha; hp.y = hb;
    __nv_bfloat162 lp; lp.x = __float2bfloat16_rn(la); lp.y = __float2bfloat16_rn(lb);
    hi = *reinterpret_cast<unsigned*>(&hp);
    lo = *reinterpret_cast<unsigned*>(&lp);
}

// One-time weight prep: W1 -> fp16x2; W12/W13/W2 -> bf16x2 hi/lo planes (pads zeroed).
__global__ void presplit_kernel(const float* __restrict__ W1,  const float* __restrict__ W12,
                                const float* __restrict__ W13, const float* __restrict__ W2)
{
    int i = blockIdx.x * 256 + threadIdx.x;
    if (i < 76800) {                                 // W1: [200][384] fp16x2
        int c = i / 384, w = i % 384;
        gW1h[i] = pack_h2(W1[c*DIN + 2*w], W1[c*DIN + 2*w + 1]);
    } else if (i < 87616) {                          // W12: [104][104]
        int j = i - 76800; int c = j / 104, w = j % 104;
        float a = 0.f, b = 0.f;
        if (c < D2 && w < 100) { a = W12[c*D1 + 2*w]; b = W12[c*D1 + 2*w + 1]; }
        split2(a, b, gW12[0][j], gW12[1][j]);
    } else if (i < 93440) {                          // W13: [104][56]
        int j = i - 87616; int c = j / 56, w = j % 56;
        float a = 0.f, b = 0.f;
        if (c < D3 && w < 50) { a = W13[c*D2 + 2*w]; b = W13[c*D2 + 2*w + 1]; }
        split2(a, b, gW13[0][j], gW13[1][j]);
    } else if (i < 122112) {                         // W2: [512][56]
        int j = i - 93440; int c = j / 56, w = j % 56;
        float a = 0.f, b = 0.f;
        if (w < 50) { a = W2[c*D3 + 2*w]; b = W2[c*D3 + 2*w + 1]; }
        split2(a, b, gW2[0][j], gW2[1][j]);
    }
}

// ---------------- cp.async helpers ----------------
__device__ __forceinline__ void cp16(unsigned* smem_dst, const unsigned* gsrc) {
    unsigned saddr = (unsigned)__cvta_generic_to_shared(smem_dst);
    asm volatile("cp.async.ca.shared.global [%0], [%1], 16;" :: "r"(saddr), "l"(gsrc));
}
#define CP_COMMIT() asm volatile("cp.async.commit_group;")
#define CP_WAIT0()  asm volatile("cp.async.wait_group 0;" ::: "memory")

__device__ __forceinline__ void stage_flat(unsigned* dHi, unsigned* dLo,
                                           const unsigned* sHi, const unsigned* sLo,
                                           int rows, int qwords, int dpitch, int spitch,
                                           int tid)
{
    for (int i = tid; i < rows * qwords; i += TH) {
        int c = i / qwords, q = i % qwords;
        cp16(&dHi[c*dpitch + q*4], &sHi[c*spitch + q*4]);
        cp16(&dLo[c*dpitch + q*4], &sLo[c*spitch + q*4]);
    }
}

// ---------------- MMA ----------------
__device__ __forceinline__ void mma_bf(float* c,
                                       unsigned a0, unsigned a1, unsigned a2, unsigned a3,
                                       unsigned b0, unsigned b1) {
    asm volatile(
        "mma.sync.aligned.m16n8k16.row.col.f32.bf16.bf16.f32 "
        "{%0,%1,%2,%3}, {%4,%5,%6,%7}, {%8,%9}, {%0,%1,%2,%3};"
        : "+f"(c[0]), "+f"(c[1]), "+f"(c[2]), "+f"(c[3])
        : "r"(a0), "r"(a1), "r"(a2), "r"(a3), "r"(b0), "r"(b1));
}
__device__ __forceinline__ void mma_f16(float* c,
                                        unsigned a0, unsigned a1, unsigned a2, unsigned a3,
                                        unsigned b0, unsigned b1) {
    asm volatile(
        "mma.sync.aligned.m16n8k16.row.col.f32.f16.f16.f32 "
        "{%0,%1,%2,%3}, {%4,%5,%6,%7}, {%8,%9}, {%0,%1,%2,%3};"
        : "+f"(c[0]), "+f"(c[1]), "+f"(c[2]), "+f"(c[3])
        : "r"(a0), "r"(a1), "r"(a2), "r"(a3), "r"(b0), "r"(b1));
}

// bf16 3-term split GEMM (layers 2-4): LDS.32 + MMA only.
template<int NT, int LDA, int LDB>
__device__ __forceinline__ void gemm_bf(float (*acc)[4],
                                        const unsigned* __restrict__ Ah,
                                        const unsigned* __restrict__ Al,
                                        const unsigned* __restrict__ Bh,
                                        const unsigned* __restrict__ Bl,
                                        int ksteps, int g, int tg)
{
    for (int ks = 0; ks < ksteps; ks++) {
        const int w0 = ks * 8;
        const int oA0 =  g      * LDA + w0 + tg;
        const int oA1 = (g + 8) * LDA + w0 + tg;
        unsigned ah0 = Ah[oA0], ah1 = Ah[oA1], ah2 = Ah[oA0 + 4], ah3 = Ah[oA1 + 4];
        unsigned al0 = Al[oA0], al1 = Al[oA1], al2 = Al[oA0 + 4], al3 = Al[oA1 + 4];
        #pragma unroll
        for (int t = 0; t < NT; t++) {
            const int bo = (t * 8 + g) * LDB + w0 + tg;
            unsigned bh0 = Bh[bo], bh1 = Bh[bo + 4];
            unsigned bl0 = Bl[bo], bl1 = Bl[bo + 4];
            mma_bf(acc[t], ah0, ah1, ah2, ah3, bh0, bh1);
            mma_bf(acc[t], ah0, ah1, ah2, ah3, bl0, bl1);
            mma_bf(acc[t], al0, al1, al2, al3, bh0, bh1);
        }
    }
}

// fp16 single-pass GEMM (layer 1): 1 MMA per tile per k-step.
template<int NT, int LDA, int LDB>
__device__ __forceinline__ void gemm_f16(float (*acc)[4],
                                         const unsigned* __restrict__ A,
                                         const unsigned* __restrict__ B,
                                         int ksteps, int g, int tg)
{
    for (int ks = 0; ks < ksteps; ks++) {
        const int w0 = ks * 8;
        unsigned a0 = A[ g      * LDA + w0 + tg    ];
        unsigned a1 = A[(g + 8) * LDA + w0 + tg    ];
        unsigned a2 = A[ g      * LDA + w0 + tg + 4];
        unsigned a3 = A[(g + 8) * LDA + w0 + tg + 4];
        #pragma unroll
        for (int t = 0; t < NT; t++) {
            const int bo = (t * 8 + g) * LDB + w0 + tg;
            mma_f16(acc[t], a0, a1, a2, a3, B[bo], B[bo + 4]);
        }
    }
}

template<int NT>
__device__ __forceinline__ void init_bias(float (*acc)[4], const float* __restrict__ bias,
                                          int n0, int tg, int nvalid)
{
    #pragma unroll
    for (int t = 0; t < NT; t++) {
        int c = n0 + t * 8 + tg * 2;
        float2 bv = make_float2(0.f, 0.f);
        if (c < nvalid) bv = *(const float2*)&bias[c];
        acc[t][0] = bv.x; acc[t][2] = bv.x;
        acc[t][1] = bv.y; acc[t][3] = bv.y;
    }
}

// relu + bf16 split + pack: cols (c, c+1) become next layer's k-pair word c/2.
template<int NT>
__device__ __forceinline__ void store_relu_bf(float (*acc)[4],
                                              unsigned* __restrict__ Hh,
                                              unsigned* __restrict__ Hl,
                                              int ldw, int m0, int n0,
                                              int g, int tg, int nvalid)
{
    #pragma unroll
    for (int t = 0; t < NT; t++) {
        int c = n0 + t * 8 + tg * 2;
        if (c < nvalid) {
            unsigned h0, l0, h1, l1;
            split2(fmaxf(acc[t][0], 0.f), fmaxf(acc[t][1], 0.f), h0, l0);
            split2(fmaxf(acc[t][2], 0.f), fmaxf(acc[t][3], 0.f), h1, l1);
            int o0 = (m0 + g) * ldw + (c >> 1);
            int o1 = (m0 + g + 8) * ldw + (c >> 1);
            Hh[o0] = h0; Hl[o0] = l0;
            Hh[o1] = h1; Hl[o1] = l1;
        }
    }
}

// x chunk global load (chunk cc covers k [cc*128, cc*128+128))
__device__ __forceinline__ float4 ldx128(const float* __restrict__ input,
                                         const float* __restrict__ h,
                                         int row0, int cc, int i)
{
    int r = i >> 5, q = i & 31;
    int k0 = cc * 128;
    const float* src; int ss;
    if (k0 < PDIM) { src = input + (size_t)row0 * PDIM + k0; ss = PDIM; }
    else           { src = h     + (size_t)row0 * HDIM + (k0 - PDIM); ss = HDIM; }
    return *(const float4*)(src + (size_t)r * ss + q * 4);
}
__device__ __forceinline__ void stx128(unsigned* x, int i, float4 v) {
    int r = i >> 5, q = i & 31;
    uint2 u;
    u.x = pack_h2(v.x, v.y);
    u.y = pack_h2(v.z, v.w);
    *(uint2*)&x[r * 68 + q * 2] = u;
}

__global__ __launch_bounds__(TH, 1)
void mlp_kernel(const float* __restrict__ input,
                const float* __restrict__ h,
                const float* __restrict__ b1,  const float* __restrict__ b12,
                const float* __restrict__ b13, const float* __restrict__ b2,
                float* __restrict__ out)
{
    extern __shared__ unsigned smem[];
    unsigned* h2Hi = smem + SM_H2;  unsigned* h2Lo = h2Hi + 3840;   // 64x60
    unsigned* h3Hi = smem + SM_H3;  unsigned* h3Lo = h3Hi + 3840;   // 64x60
    unsigned* h1Hi = smem + SM_H1;  unsigned* h1Lo = h1Hi + 6912;   // 64x108

    const int tid  = threadIdx.x;
    const int lane = tid & 31;
    const int wid  = tid >> 5;     // 0..15
    const int g    = lane >> 2;
    const int tg   = lane & 3;
    const int rowg = wid >> 2;     // 0..3
    const int nq   = wid & 3;      // n-quarter
    const int m0   = rowg * 16;
    const int row0 = blockIdx.x * ROWS;

    float acc[7][4];

    const int L1_N0[4]  = {0, 56, 104, 152};   // 25 tiles -> {7,6,6,6}
    const int L23_N0[4] = {0, 32, 56, 80};     // 13 tiles -> {4,3,3,3}

    // ===================== Layer 1: [64x768] @ W1^T -> relu [64x200], fp16 single ==========
    if (nq == 0) init_bias<7>(acc, b1, 0, tg, D1);
    else         init_bias<6>(acc, b1, L1_N0[nq], tg, D1);

    // prologue: stage chunk 0 into buf0
    {
        unsigned* buf = smem;
        for (int i = tid; i < 200 * 16; i += TH) {
            int c = i >> 4, q = i & 15;
            cp16(&buf[BW1 + c*68 + q*4], &gW1h[c*384 + q*4]);
        }
        CP_COMMIT();
        float4 xv[4];
        #pragma unroll
        for (int j = 0; j < 4; j++) xv[j] = ldx128(input, h, row0, 0, tid + j*TH);
        #pragma unroll
        for (int j = 0; j < 4; j++) stx128(buf + BX1, tid + j*TH, xv[j]);
        CP_WAIT0();
    }
    __syncthreads();

    #pragma unroll 1
    for (int ch = 0; ch < 6; ch++) {
        unsigned* cur = smem + (ch & 1) * BUF1SZ;
        unsigned* nxt = smem + ((ch + 1) & 1) * BUF1SZ;
        float4 xv[4];
        if (ch < 5) {
            for (int i = tid; i < 200 * 16; i += TH) {
                int c = i >> 4, q = i & 15;
                cp16(&nxt[BW1 + c*68 + q*4], &gW1h[c*384 + (ch+1)*64 + q*4]);
            }
            CP_COMMIT();
            #pragma unroll
            for (int j = 0; j < 4; j++) xv[j] = ldx128(input, h, row0, ch + 1, tid + j*TH);
        }
        // compute chunk ch (8 k-steps of 16)
        {
            const unsigned* A = cur + BX1 + m0 * 68;
            int o = L1_N0[nq] * 68;
            if (nq == 0) gemm_f16<7, 68, 68>(acc, A, cur + BW1, 8, g, tg);
            else         gemm_f16<6, 68, 68>(acc, A, cur + BW1 + o, 8, g, tg);
        }
        if (ch < 5) {
            #pragma unroll
            for (int j = 0; j < 4; j++) stx128(nxt + BX1, tid + j*TH, xv[j]);
            CP_WAIT0();
        }
        __syncthreads();
    }

    // h1 store (region above buffers) + stage W12 + zero pads; single barrier
    if (nq == 0) store_relu_bf<7>(acc, h1Hi, h1Lo, 108, m0, 0, g, tg, D1);
    else         store_relu_bf<6>(acc, h1Hi, h1Lo, 108, m0, L1_N0[nq], g, tg, D1);
    {
        unsigned* wHi = smem + SM_W;          // W12 planes pitch 108 (11232 words each)
        unsigned* wLo = wHi + 11232;
        stage_flat(wHi, wLo, gW12[0], gW12[1], 104, 26, 108, 104, tid);
        CP_COMMIT();
        // zero pads: h1 words 100..103, h2/h3 words 50..55 (L1 buffers dead now)
        for (int i = tid; i < 64 * 4; i += TH) {
            int r = i >> 2, w = 100 + (i & 3);
            h1Hi[r * 108 + w] = 0; h1Lo[r * 108 + w] = 0;
        }
        for (int i = tid; i < 64 * 6; i += TH) {
            int r = i / 6, w = 50 + (i % 6);
            h2Hi[r * 60 + w] = 0; h2Lo[r * 60 + w] = 0;
            h3Hi[r * 60 + w] = 0; h3Lo[r * 60 + w] = 0;
        }
        CP_WAIT0();
    }
    __syncthreads();

    // ===================== Layer 2: [64x200] @ W12^T -> relu [64x100] =====================
    {
        unsigned* wHi = smem + SM_W; unsigned* wLo = wHi + 11232;
        const unsigned* Ah = h1Hi + m0 * 108;
        const unsigned* Al = h1Lo + m0 * 108;
        int o = L23_N0[nq] * 108;
        if (nq == 0) {
            init_bias<4>(acc, b12, 0, tg, D2);
            gemm_bf<4, 108, 108>(acc, Ah, Al, wHi + o, wLo + o, 13, g, tg);
            store_relu_bf<4>(acc, h2Hi, h2Lo, 60, m0, 0, g, tg, D2);
        } else {
            init_bias<3>(acc, b12, L23_N0[nq], tg, D2);
            gemm_bf<3, 108, 108>(acc, Ah, Al, wHi + o, wLo + o, 13, g, tg);
            store_relu_bf<3>(acc, h2Hi, h2Lo, 60, m0, L23_N0[nq], g, tg, D2);
        }
    }
    __syncthreads();

    // stage W13 (pitch 60, 6240 words/plane)
    {
        unsigned* wHi = smem + SM_W; unsigned* wLo = wHi + 6240;
        stage_flat(wHi, wLo, gW13[0], gW13[1], 104, 14, 60, 56, tid);
        CP_COMMIT(); CP_WAIT0();
    }
    __syncthreads();

    // ===================== Layer 3: [64x100] @ W13^T -> relu [64x100] =====================
    {
        unsigned* wHi = smem + SM_W; unsigned* wLo = wHi + 6240;
        const unsigned* Ah = h2Hi + m0 * 60;
        const unsigned* Al = h2Lo + m0 * 60;
        int o = L23_N0[nq] * 60;
        if (nq == 0) {
            init_bias<4>(acc, b13, 0, tg, D3);
            gemm_bf<4, 60, 60>(acc, Ah, Al, wHi + o, wLo + o, 7, g, tg);
            store_relu_bf<4>(acc, h3Hi, h3Lo, 60, m0, 0, g, tg, D3);
        } else {
            init_bias<3>(acc, b13, L23_N0[nq], tg, D3);
            gemm_bf<3, 60, 60>(acc, Ah, Al, wHi + o, wLo + o, 7, g, tg);
            store_relu_bf<3>(acc, h3Hi, h3Lo, 60, m0, L23_N0[nq], g, tg, D3);
        }
    }
    __syncthreads();

    // ===================== Layer 4: 8 chunks of 64 cols, double-buffered ==================
    {
        unsigned* bufA = smem + SM_W;
        stage_flat(bufA, bufA + 3840, gW2[0], gW2[1], 64, 14, 60, 56, tid);
        CP_COMMIT(); CP_WAIT0();
    }
    __syncthreads();

    float dd = 0.f;
    #pragma unroll 1
    for (int c4 = 0; c4 < 8; c4++) {
        unsigned* cur = smem + SM_W + (c4 & 1) * 7680;
        unsigned* nxt = smem + SM_W + ((c4 + 1) & 1) * 7680;
        if (c4 < 7) {
            stage_flat(nxt, nxt + 3840, gW2[0] + (c4 + 1) * 64 * 56,
                       gW2[1] + (c4 + 1) * 64 * 56, 64, 14, 60, 56, tid);
            CP_COMMIT();
        }
        init_bias<2>(acc, b2, c4 * 64 + nq * 16, tg, DOUT);
        {
            const unsigned* Ah = h3Hi + m0 * 60;
            const unsigned* Al = h3Lo + m0 * 60;
            int o = nq * 16 * 60;
            gemm_bf<2, 60, 60>(acc, Ah, Al, cur + o, cur + 3840 + o, 7, g, tg);
        }
        #pragma unroll
        for (int t = 0; t < 2; t++) {
            int c  = c4 * 64 + nq * 16 + t * 8 + tg * 2;
            int r1 = row0 + m0 + g;
            int r2 = r1 + 8;
            float2 v0 = make_float2(acc[t][0], acc[t][1]);
            float2 v1 = make_float2(acc[t][2], acc[t][3]);
            *(float2*)&out[(size_t)r1 * PDIM + c] = v0;
            *(float2*)&out[(size_t)r2 * PDIM + c] = v1;
            if (r1 < NROWS - 1) {
                float2 nx = *(const float2*)&input[(size_t)(r1 + 1) * PDIM + c];
                float d0 = v0.x - nx.x, d1 = v0.y - nx.y;
                dd += d0 * d0 + d1 * d1;
            }
            if (r2 < NROWS - 1) {
                float2 nx = *(const float2*)&input[(size_t)(r2 + 1) * PDIM + c];
                float d0 = v1.x - nx.x, d1 = v1.y - nx.y;
                dd += d0 * d0 + d1 * d1;
            }
        }
        if (c4 < 7) CP_WAIT0();
        __syncthreads();
    }

    // reduce dd -> g_part0
    #pragma unroll
    for (int off = 16; off > 0; off >>= 1)
        dd += __shfl_down_sync(0xFFFFFFFFu, dd, off);
    __shared__ float wdd[16];
    if (lane == 0) wdd[wid] = dd;
    __syncthreads();
    if (tid == 0) {
        float s = 0.f;
        #pragma unroll
        for (int w = 0; w < 16; w++) s += wdd[w];
        atomicAdd(&g_part0, (double)s);
    }
}

// h statistics: column sums (mu), sum of squares (S), total variation (diff)
__global__ __launch_bounds__(HDIM)
void hred_kernel(const float* __restrict__ h)
{
    const int c  = threadIdx.x;
    const int r0 = blockIdx.x * 256;
    float prev = (r0 > 0) ? h[(size_t)(r0 - 1) * HDIM + c] : 0.f;
    float cs = 0.f, sq = 0.f, df = 0.f;
    #pragma unroll 4
    for (int i = 0; i < 256; i++) {
        float v = h[(size_t)(r0 + i) * HDIM + c];
        cs += v;
        sq += v * v;
        if (r0 + i > 0) df += fabsf(v - prev);
        prev = v;
    }
    atomicAdd(&g_mu[c], (double)cs);

    #pragma unroll
    for (int off = 16; off > 0; off >>= 1) {
        sq += __shfl_down_sync(0xFFFFFFFFu, sq, off);
        df += __shfl_down_sync(0xFFFFFFFFu, df, off);
    }
    __shared__ float wsq[8], wdf[8];
    int tx = c & 31, ty = c >> 5;
    if (tx == 0) { wsq[ty] = sq; wdf[ty] = df; }
    __syncthreads();
    if (c == 0) {
        float s1 = 0.f, s2 = 0.f;
        #pragma unroll
        for (int w = 0; w < 8; w++) { s1 += wsq[w]; s2 += wdf[w]; }
        atomicAdd(&g_S, (double)s1);
        atomicAdd(&g_diff, (double)s2);
    }
}

__global__ void finalize_kernel(float* __restrict__ out, long long base)
{
    __shared__ double red[HDIM];
    int t = threadIdx.x;
    red[t] = fabs(g_mu[t]);
    __syncthreads();
    for (int s = 128; s > 0; s >>= 1) {
        if (t < s) red[t] += red[t + s];
        __syncthreads();
    }
    if (t == 0) {
        const double Nn = (double)NROWS;
        out[base + 0] = (float)(sqrt(g_part0) / (Nn - 1.0));
        out[base + 1] = (float)(red[0] / Nn / (double)HDIM);
        out[base + 2] = (float)fabs(g_S / Nn / (double)HDIM - 1.0);
        out[base + 3] = (float)(g_diff / (Nn - 1.0) / (double)HDIM);
    }
}

extern "C" void kernel_launch(void* const* d_in, const int* in_sizes, int n_in,
                              void* d_out, int out_size)
{
    const float* input = (const float*)d_in[0];
    const float* h     = (const float*)d_in[1];
    const float* W1    = (const float*)d_in[2];
    const float* b1    = (const float*)d_in[3];
    const float* W12   = (const float*)d_in[4];
    const float* b12   = (const float*)d_in[5];
    const float* W13   = (const float*)d_in[6];
    const float* b13   = (const float*)d_in[7];
    const float* W2    = (const float*)d_in[8];
    const float* b2    = (const float*)d_in[9];
    float* out = (float*)d_out;

    cudaFuncSetAttribute(mlp_kernel, cudaFuncAttributeMaxDynamicSharedMemorySize, SMEM_BYTES);

    zero_kernel<<<1, 256>>>();
    presplit_kernel<<<478, 256>>>(W1, W12, W13, W2);
    hred_kernel<<<NROWS / 256, HDIM>>>(h);
    mlp_kernel<<<NROWS / ROWS, TH, SMEM_BYTES>>>(input, h, b1, b12, b13, b2, out);
    finalize_kernel<<<1, HDIM>>>(out, (long long)out_size - 4);
}